// round 16
// baseline (speedup 1.0000x reference)
#include <cuda_runtime.h>
#include <cuda_bf16.h>
#include <stdint.h>

#define DDIM   512
#define KLAT   64
#define NCODE  1024
#define ROWS   128
#define NTHR   128
#define KT     32
#define XS_STRIDE 132
#define PW     36            // padded word stride (144 B) for bf16 plane rows

// smem byte offsets
#define SM_AH    0           // z hi plane:  128 rows * 144 B = 18432
#define SM_AL    18432       // z lo plane
#define SM_BH    36864       // code hi plane (128-code tile)
#define SM_BL    55296       // code lo plane
#define SM_CSQ   73728       // 128 floats (0.5*csq of tile)
#define SM_SIDX  74240       // 128 ints
#define SM_TOTAL 74752

__device__ float g_dec[NCODE * DDIM];                    // codebook @ U^T
__device__ float g_csq[NCODE];
__device__ __align__(16) uint16_t g_cbh[NCODE * KLAT];   // bf16 hi plane of codebook
__device__ __align__(16) uint16_t g_cbl[NCODE * KLAT];   // bf16 lo plane

typedef unsigned long long u64;
static __device__ __forceinline__ u64 pk2(float x, float y) {
    u64 r; asm("mov.b64 %0, {%1, %2};" : "=l"(r) : "f"(x), "f"(y)); return r;
}
static __device__ __forceinline__ float2 upk2(u64 v) {
    float2 f; asm("mov.b64 {%0, %1}, %2;" : "=f"(f.x), "=f"(f.y) : "l"(v)); return f;
}
static __device__ __forceinline__ void ffma2(u64 &d, u64 a, u64 b) {
    asm("fma.rn.f32x2 %0, %1, %2, %0;" : "+l"(d) : "l"(a), "l"(b));
}
#define MMA_BF16(d, a, b0_, b1_) \
    asm volatile("mma.sync.aligned.m16n8k16.row.col.f32.bf16.bf16.f32 " \
        "{%0,%1,%2,%3}, {%4,%5,%6,%7}, {%8,%9}, {%0,%1,%2,%3};" \
        : "+f"((d)[0]), "+f"((d)[1]), "+f"((d)[2]), "+f"((d)[3]) \
        : "r"((a)[0]), "r"((a)[1]), "r"((a)[2]), "r"((a)[3]), "r"(b0_), "r"(b1_))

static __device__ __forceinline__ void ldsm_x4(uint32_t* r, uint32_t saddr) {
    asm volatile("ldmatrix.sync.aligned.m8n8.x4.shared.b16 {%0,%1,%2,%3}, [%4];"
        : "=r"(r[0]), "=r"(r[1]), "=r"(r[2]), "=r"(r[3]) : "r"(saddr));
}
static __device__ __forceinline__ uint32_t smem_u32_of(const void* p) {
    uint32_t a;
    asm("{ .reg .u64 t; cvta.to.shared.u64 t, %1; cvt.u32.u64 %0, t; }" : "=r"(a) : "l"(p));
    return a;
}
static __device__ __forceinline__ uint32_t pack_bf16x2(float lo, float hi) {
    return (uint32_t)__bfloat16_as_ushort(__float2bfloat16(lo)) |
           ((uint32_t)__bfloat16_as_ushort(__float2bfloat16(hi)) << 16);
}

// sortable key: larger score -> larger key; tie -> lower pair id wins
static __device__ __forceinline__ void upd2(u64& k1, u64& k2, float s, int pid) {
    uint32_t u = __float_as_uint(s);
    u ^= (uint32_t)((int32_t)u >> 31) | 0x80000000u;
    u64 k = ((u64)u << 32) | (uint32_t)(511 - pid);
    u64 mx = k > k1 ? k : k1;
    u64 mn = k > k1 ? k1 : k;
    k1 = mx;
    k2 = mn > k2 ? mn : k2;
}
static __device__ __forceinline__ float unkey(uint32_t u) {
    uint32_t v = (u & 0x80000000u) ? (u ^ 0x80000000u) : ~u;
    return __uint_as_float(v);
}

// Prep: decode table, csq, bf16 hi/lo planes of the codebook (row-major).
__global__ void prep_kernel(const float* __restrict__ U, const float* __restrict__ cb) {
    __shared__ float code[KLAT];
    const int c = blockIdx.x;
    const int tid = threadIdx.x;   // 128
    if (tid < KLAT / 4)
        ((float4*)code)[tid] = ((const float4*)(cb + c * KLAT))[tid];
    __syncthreads();
    if (tid == 0) {
        float s = 0.f;
        #pragma unroll
        for (int k = 0; k < KLAT; k++) s = fmaf(code[k], code[k], s);
        g_csq[c] = s;
    }
    if (tid < KLAT) {
        float v = code[tid];
        __nv_bfloat16 h = __float2bfloat16(v);
        float r1 = v - __bfloat162float(h);
        g_cbh[c * KLAT + tid] = __bfloat16_as_ushort(h);
        g_cbl[c * KLAT + tid] = __bfloat16_as_ushort(__float2bfloat16(r1));
    }
    #pragma unroll
    for (int i = 0; i < 4; i++) {
        const int d = tid + i * 128;
        const float4* u4 = (const float4*)(U + d * KLAT);
        float s = 0.f;
        #pragma unroll
        for (int q = 0; q < KLAT / 4; q++) {
            float4 u = u4[q];
            float4 cv = ((const float4*)code)[q];
            s = fmaf(u.x, cv.x, s); s = fmaf(u.y, cv.y, s);
            s = fmaf(u.z, cv.z, s); s = fmaf(u.w, cv.w, s);
        }
        g_dec[c * DDIM + d] = s;
    }
}

// exact transformed score (maximize): dot(z,c) - 0.5*||c||^2, pure fp32
static __device__ float exact_sc(const float* __restrict__ z,
                                 const float* __restrict__ cb, int idx) {
    const float* cr = cb + (size_t)idx * KLAT;
    float d = 0.f;
    #pragma unroll
    for (int k = 0; k < KLAT; k++) d = fmaf(z[k], __ldg(&cr[k]), d);
    return d - 0.5f * __ldg(&g_csq[idx]);
}
static __device__ __forceinline__ bool better(float sa, int ia, float sb, int ib) {
    return sa > sb || (sa == sb && ia < ib);
}

__global__ void __launch_bounds__(NTHR, 3)
vqvae_main(const float* __restrict__ x,
           const float* __restrict__ U,
           const float* __restrict__ cb,
           float* __restrict__ out,
           int B)
{
    extern __shared__ char smc[];
    uint32_t* AH    = (uint32_t*)(smc + SM_AH);
    uint32_t* AL    = (uint32_t*)(smc + SM_AL);
    uint32_t* BH    = (uint32_t*)(smc + SM_BH);
    uint32_t* BL    = (uint32_t*)(smc + SM_BL);
    float*    csq2s = (float*)(smc + SM_CSQ);
    int*      sidx  = (int*)(smc + SM_SIDX);
    float*    xs_t  = (float*)(smc + SM_AH);           // phase A overlay
    float*    us    = (float*)(smc + SM_AH + 17424);   // phase A overlay

    const int tid = threadIdx.x;
    const int R0  = blockIdx.x * ROWS;
    const int ty  = tid >> 3;
    const int tx  = tid & 7;
    const uint32_t sbase = smem_u32_of(smc);

    const size_t Z_OFF   = (size_t)B * DDIM;
    const size_t ZQ_OFF  = Z_OFF + (size_t)B * KLAT;
    const size_t IDX_OFF = ZQ_OFF + (size_t)B * KLAT;

    // ---------------- Phase A: z = x @ U (FFMA2, proven) ----------------
    u64 acc2[8][4];
    #pragma unroll
    for (int i = 0; i < 8; i++)
        #pragma unroll
        for (int p = 0; p < 4; p++) acc2[i][p] = 0ull;

    const float4* x4 = (const float4*)x;
    const float4* U4 = (const float4*)U;

    for (int kk = 0; kk < DDIM; kk += KT) {
        #pragma unroll
        for (int j = 0; j < 8; j++) {
            int l4  = j * NTHR + tid;
            int row = l4 >> 3;
            int k4  = l4 & 7;
            float4 v = x4[(size_t)(R0 + row) * (DDIM / 4) + (kk >> 2) + k4];
            xs_t[(4 * k4 + 0) * XS_STRIDE + row] = v.x;
            xs_t[(4 * k4 + 1) * XS_STRIDE + row] = v.y;
            xs_t[(4 * k4 + 2) * XS_STRIDE + row] = v.z;
            xs_t[(4 * k4 + 3) * XS_STRIDE + row] = v.w;
        }
        #pragma unroll
        for (int j = 0; j < 4; j++) {
            int l4 = j * NTHR + tid;
            int kr = l4 >> 4;
            int c4 = l4 & 15;
            ((float4*)us)[kr * 16 + c4] = U4[(kk + kr) * 16 + c4];
        }
        __syncthreads();
        #pragma unroll 8
        for (int k = 0; k < KT; k++) {
            float4 a0 = *(const float4*)&xs_t[k * XS_STRIDE + ty * 8];
            float4 a1 = *(const float4*)&xs_t[k * XS_STRIDE + ty * 8 + 4];
            ulonglong2 b01 = *(const ulonglong2*)&us[k * 64 + tx * 8];
            ulonglong2 b23 = *(const ulonglong2*)&us[k * 64 + tx * 8 + 4];
            u64 bp[4] = {b01.x, b01.y, b23.x, b23.y};
            float a[8] = {a0.x, a0.y, a0.z, a0.w, a1.x, a1.y, a1.z, a1.w};
            #pragma unroll
            for (int i = 0; i < 8; i++) {
                u64 ad = pk2(a[i], a[i]);
                #pragma unroll
                for (int p = 0; p < 4; p++) ffma2(acc2[i][p], ad, bp[p]);
            }
        }
        __syncthreads();
    }

    // z -> gmem (fp32) and bf16 hi/lo A-plane smem
    {
        float4* oz = (float4*)(out + Z_OFF);
        #pragma unroll
        for (int i = 0; i < 8; i++) {
            int row = ty * 8 + i;
            float2 v0 = upk2(acc2[i][0]), v1 = upk2(acc2[i][1]);
            float2 v2 = upk2(acc2[i][2]), v3 = upk2(acc2[i][3]);
            oz[(size_t)(R0 + row) * 16 + tx * 2]     = make_float4(v0.x, v0.y, v1.x, v1.y);
            oz[(size_t)(R0 + row) * 16 + tx * 2 + 1] = make_float4(v2.x, v2.y, v3.x, v3.y);
            float zf[8] = {v0.x, v0.y, v1.x, v1.y, v2.x, v2.y, v3.x, v3.y};
            #pragma unroll
            for (int p = 0; p < 4; p++) {
                float e0 = zf[2 * p], e1 = zf[2 * p + 1];
                float h0 = __bfloat162float(__float2bfloat16(e0));
                float h1 = __bfloat162float(__float2bfloat16(e1));
                AH[row * PW + tx * 4 + p] = pack_bf16x2(e0, e1);
                AL[row * PW + tx * 4 + p] = pack_bf16x2(e0 - h0, e1 - h1);
            }
        }
    }
    __threadfence_block();
    __syncthreads();

    // ---------------- Phase B: HMMA scores, ldmatrix fragments, keyed top-2 ----------------
    const int lane = tid & 31;
    const int w    = tid >> 5;
    const int g    = lane >> 2;
    const int t    = lane & 3;

    // ldmatrix per-lane address offsets (bytes) within a plane
    const uint32_t rowA_off = (uint32_t)((w * 32 + ((lane >> 3) & 1) * 8 + (lane & 7)) * 144
                                         + ((lane >> 4) & 1) * 16);
    const uint32_t rowB_off = (uint32_t)((((lane >> 4) & 1) * 8 + (lane & 7)) * 144
                                         + ((lane >> 3) & 1) * 16);
    const uint32_t AHs = sbase + SM_AH, ALs = sbase + SM_AL;
    const uint32_t BHs = sbase + SM_BH, BLs = sbase + SM_BL;

    u64 key1[4], key2[4];
    #pragma unroll
    for (int s = 0; s < 4; s++) { key1[s] = 0ull; key2[s] = 0ull; }

    for (int ct = 0; ct < NCODE; ct += 128) {
        // load 128-code tile (hi+lo planes) into padded smem; 0.5*csq
        {
            const uint4* srch = (const uint4*)(g_cbh + (size_t)(ct + tid) * KLAT);
            const uint4* srcl = (const uint4*)(g_cbl + (size_t)(ct + tid) * KLAT);
            uint32_t* dsth = BH + tid * PW;
            uint32_t* dstl = BL + tid * PW;
            #pragma unroll
            for (int j = 0; j < 8; j++) {
                *(uint4*)(dsth + j * 4) = srch[j];
                *(uint4*)(dstl + j * 4) = srcl[j];
            }
            csq2s[tid] = 0.5f * g_csq[ct + tid];
        }
        __syncthreads();

        #pragma unroll 1
        for (int pass = 0; pass < 4; pass++) {
            float D[2][4][4];
            #pragma unroll
            for (int m = 0; m < 2; m++)
                #pragma unroll
                for (int n8 = 0; n8 < 4; n8++)
                    #pragma unroll
                    for (int q = 0; q < 4; q++) D[m][n8][q] = 0.f;

            #pragma unroll
            for (int k = 0; k < 4; k++) {
                uint32_t ah[2][4], al[2][4];
                #pragma unroll
                for (int m = 0; m < 2; m++) {
                    ldsm_x4(ah[m], AHs + rowA_off + m * 2304 + k * 32);
                    ldsm_x4(al[m], ALs + rowA_off + m * 2304 + k * 32);
                }
                #pragma unroll
                for (int j = 0; j < 2; j++) {
                    uint32_t bh[4], bl[4];
                    uint32_t bo = (uint32_t)((pass * 32 + j * 16) * 144 + k * 32);
                    ldsm_x4(bh, BHs + rowB_off + bo);
                    ldsm_x4(bl, BLs + rowB_off + bo);
                    #pragma unroll
                    for (int m = 0; m < 2; m++) {
                        MMA_BF16(D[m][2 * j],     ah[m], bh[0], bh[1]);
                        MMA_BF16(D[m][2 * j],     al[m], bh[0], bh[1]);
                        MMA_BF16(D[m][2 * j],     ah[m], bl[0], bl[1]);
                        MMA_BF16(D[m][2 * j + 1], ah[m], bh[2], bh[3]);
                        MMA_BF16(D[m][2 * j + 1], al[m], bh[2], bh[3]);
                        MMA_BF16(D[m][2 * j + 1], ah[m], bl[2], bl[3]);
                    }
                }
            }

            // branchless pair-keyed top-2 (pair = codes c, c+1; c even)
            #pragma unroll
            for (int n8 = 0; n8 < 4; n8++) {
                int cl_ = pass * 32 + n8 * 8 + 2 * t;
                float2 cq = *(const float2*)&csq2s[cl_];
                int pid = (ct + cl_) >> 1;
                #pragma unroll
                for (int m = 0; m < 2; m++) {
                    float s0 = fmaxf(D[m][n8][0] - cq.x, D[m][n8][1] - cq.y);
                    upd2(key1[m * 2],     key2[m * 2],     s0, pid);
                    float s1 = fmaxf(D[m][n8][2] - cq.x, D[m][n8][3] - cq.y);
                    upd2(key1[m * 2 + 1], key2[m * 2 + 1], s1, pid);
                }
            }
        }
        __syncthreads();   // before next tile overwrites BH/BL
    }

    // merge top-2 keys across the 4 threads sharing each row (shfl width 4)
    #pragma unroll
    for (int s = 0; s < 4; s++) {
        #pragma unroll
        for (int off = 2; off > 0; off >>= 1) {
            u64 k1b = __shfl_down_sync(0xffffffffu, key1[s], off, 4);
            u64 k2b = __shfl_down_sync(0xffffffffu, key2[s], off, 4);
            u64 m1 = key1[s] > k1b ? key1[s] : k1b;
            u64 lo = key1[s] > k1b ? k1b : key1[s];
            u64 mm = key2[s] > k2b ? key2[s] : k2b;
            key2[s] = lo > mm ? lo : mm;
            key1[s] = m1;
        }
    }
    if (t == 0) {
        #pragma unroll
        for (int s = 0; s < 4; s++) {
            int row = w * 32 + (s >> 1) * 16 + (s & 1) * 8 + g;
            const float* zr = out + Z_OFF + (size_t)(R0 + row) * KLAT;
            int pid1 = 511 - (int)(uint32_t)key1[s];
            int c1 = pid1 * 2;
            float ea = exact_sc(zr, cb, c1);
            float eb = exact_sc(zr, cb, c1 + 1);
            int   fi = (eb > ea) ? (c1 + 1) : c1;
            float fe = (eb > ea) ? eb : ea;
            float s1f = unkey((uint32_t)(key1[s] >> 32));
            float s2f = unkey((uint32_t)(key2[s] >> 32));
            if (s1f - s2f < 1e-2f) {            // guarded: exact-check runner-up pair
                int pid2 = 511 - (int)(uint32_t)key2[s];
                int c2 = pid2 * 2;
                float ec = exact_sc(zr, cb, c2);
                float ed = exact_sc(zr, cb, c2 + 1);
                if (better(ec, c2,     fe, fi)) { fe = ec; fi = c2; }
                if (better(ed, c2 + 1, fe, fi)) { fe = ed; fi = c2 + 1; }
            }
            sidx[row] = fi;
        }
    }
    __syncthreads();

    // ---------------- Phase C: outputs [x_recon | z_q_ste | indices] ----------------
    out[IDX_OFF + R0 + tid] = (float)sidx[tid];

    const int lane2 = tid & 31;
    const float2* cb2  = (const float2*)cb;
    const float4* dec4 = (const float4*)g_dec;
    float2* ozq = (float2*)(out + ZQ_OFF);
    float4* ox  = (float4*)out;
    const float* zg = out + Z_OFF;
    for (int r = 0; r < 32; r++) {
        int row = w * 32 + r;
        int idx = sidx[row];
        float2 zv = *(const float2*)(zg + (size_t)(R0 + row) * KLAT + 2 * lane2);
        float2 cv = cb2[(size_t)idx * (KLAT / 2) + lane2];
        float2 o;
        o.x = zv.x + (cv.x - zv.x);          // STE numerics
        o.y = zv.y + (cv.y - zv.y);
        ozq[(size_t)(R0 + row) * (KLAT / 2) + lane2] = o;
        #pragma unroll
        for (int j = 0; j < 4; j++)
            ox[(size_t)(R0 + row) * (DDIM / 4) + j * 32 + lane2] =
                dec4[(size_t)idx * (DDIM / 4) + j * 32 + lane2];
    }
}

extern "C" void kernel_launch(void* const* d_in, const int* in_sizes, int n_in,
                              void* d_out, int out_size) {
    const float *x = 0, *U = 0, *cb = 0;
    int xsize = 0;
    for (int i = 0; i < n_in; i++) {
        if (in_sizes[i] == DDIM * KLAT)       U  = (const float*)d_in[i];
        else if (in_sizes[i] == NCODE * KLAT) cb = (const float*)d_in[i];
        else { x = (const float*)d_in[i]; xsize = in_sizes[i]; }
    }
    float* out = (float*)d_out;
    const int B = xsize / DDIM;

    cudaFuncSetAttribute(vqvae_main, cudaFuncAttributeMaxDynamicSharedMemorySize, SM_TOTAL);
    prep_kernel<<<NCODE, 128>>>(U, cb);
    vqvae_main<<<B / ROWS, NTHR, SM_TOTAL>>>(x, U, cb, out, B);
}

// round 17
// speedup vs baseline: 1.1915x; 1.1915x over previous
#include <cuda_runtime.h>
#include <cuda_bf16.h>
#include <stdint.h>

#define DDIM   512
#define KLAT   64
#define NCODE  1024
#define ROWS   128
#define NTHR   128
#define KT     32
#define XS_STRIDE 132
#define PW     36            // padded word stride (144 B) for bf16 plane rows

// kernel-2 smem byte offsets (dynamic)
#define SM_AH    0           // z hi plane:  128 rows * 144 B = 18432
#define SM_AL    18432       // z lo plane
#define SM_BH    36864       // code hi plane (64-code tile): 64*144 = 9216
#define SM_BL    46080       // code lo plane
#define SM_CSQ   55296       // 64 floats (0.5*csq of tile)
#define SM_SIDX  55552       // 128 ints
#define SM_TOTAL 56064

__device__ float g_dec[NCODE * DDIM];                    // codebook @ U^T
__device__ float g_csq[NCODE];
__device__ __align__(16) uint16_t g_cbh[NCODE * KLAT];   // bf16 hi plane of codebook
__device__ __align__(16) uint16_t g_cbl[NCODE * KLAT];   // bf16 lo plane

typedef unsigned long long u64;
static __device__ __forceinline__ u64 pk2(float x, float y) {
    u64 r; asm("mov.b64 %0, {%1, %2};" : "=l"(r) : "f"(x), "f"(y)); return r;
}
static __device__ __forceinline__ float2 upk2(u64 v) {
    float2 f; asm("mov.b64 {%0, %1}, %2;" : "=f"(f.x), "=f"(f.y) : "l"(v)); return f;
}
static __device__ __forceinline__ void ffma2(u64 &d, u64 a, u64 b) {
    asm("fma.rn.f32x2 %0, %1, %2, %0;" : "+l"(d) : "l"(a), "l"(b));
}
#define MMA_BF16(d, a, b0_, b1_) \
    asm volatile("mma.sync.aligned.m16n8k16.row.col.f32.bf16.bf16.f32 " \
        "{%0,%1,%2,%3}, {%4,%5,%6,%7}, {%8,%9}, {%0,%1,%2,%3};" \
        : "+f"((d)[0]), "+f"((d)[1]), "+f"((d)[2]), "+f"((d)[3]) \
        : "r"((a)[0]), "r"((a)[1]), "r"((a)[2]), "r"((a)[3]), "r"(b0_), "r"(b1_))

static __device__ __forceinline__ void ldsm_x4(uint32_t* r, uint32_t saddr) {
    asm volatile("ldmatrix.sync.aligned.m8n8.x4.shared.b16 {%0,%1,%2,%3}, [%4];"
        : "=r"(r[0]), "=r"(r[1]), "=r"(r[2]), "=r"(r[3]) : "r"(saddr));
}
static __device__ __forceinline__ uint32_t smem_u32_of(const void* p) {
    uint32_t a;
    asm("{ .reg .u64 t; cvta.to.shared.u64 t, %1; cvt.u32.u64 %0, t; }" : "=r"(a) : "l"(p));
    return a;
}
static __device__ __forceinline__ uint32_t pack_bf16x2(float lo, float hi) {
    return (uint32_t)__bfloat16_as_ushort(__float2bfloat16(lo)) |
           ((uint32_t)__bfloat16_as_ushort(__float2bfloat16(hi)) << 16);
}

// sortable key: larger score -> larger key; tie -> lower pair id wins
static __device__ __forceinline__ void upd2(u64& k1, u64& k2, float s, int pid) {
    uint32_t u = __float_as_uint(s);
    u ^= (uint32_t)((int32_t)u >> 31) | 0x80000000u;
    u64 k = ((u64)u << 32) | (uint32_t)(511 - pid);
    u64 mx = k > k1 ? k : k1;
    u64 mn = k > k1 ? k1 : k;
    k1 = mx;
    k2 = mn > k2 ? mn : k2;
}
static __device__ __forceinline__ float unkey(uint32_t u) {
    uint32_t v = (u & 0x80000000u) ? (u ^ 0x80000000u) : ~u;
    return __uint_as_float(v);
}

// Prep: decode table, csq, bf16 hi/lo planes of the codebook (row-major).
__global__ void prep_kernel(const float* __restrict__ U, const float* __restrict__ cb) {
    __shared__ float code[KLAT];
    const int c = blockIdx.x;
    const int tid = threadIdx.x;   // 128
    if (tid < KLAT / 4)
        ((float4*)code)[tid] = ((const float4*)(cb + c * KLAT))[tid];
    __syncthreads();
    if (tid == 0) {
        float s = 0.f;
        #pragma unroll
        for (int k = 0; k < KLAT; k++) s = fmaf(code[k], code[k], s);
        g_csq[c] = s;
    }
    if (tid < KLAT) {
        float v = code[tid];
        __nv_bfloat16 h = __float2bfloat16(v);
        float r1 = v - __bfloat162float(h);
        g_cbh[c * KLAT + tid] = __bfloat16_as_ushort(h);
        g_cbl[c * KLAT + tid] = __bfloat16_as_ushort(__float2bfloat16(r1));
    }
    #pragma unroll
    for (int i = 0; i < 4; i++) {
        const int d = tid + i * 128;
        const float4* u4 = (const float4*)(U + d * KLAT);
        float s = 0.f;
        #pragma unroll
        for (int q = 0; q < KLAT / 4; q++) {
            float4 u = u4[q];
            float4 cv = ((const float4*)code)[q];
            s = fmaf(u.x, cv.x, s); s = fmaf(u.y, cv.y, s);
            s = fmaf(u.z, cv.z, s); s = fmaf(u.w, cv.w, s);
        }
        g_dec[c * DDIM + d] = s;
    }
}

// exact transformed score (maximize): dot(z,c) - 0.5*||c||^2, pure fp32
static __device__ float exact_sc(const float* __restrict__ z,
                                 const float* __restrict__ cb, int idx) {
    const float* cr = cb + (size_t)idx * KLAT;
    float d = 0.f;
    #pragma unroll
    for (int k = 0; k < KLAT; k++) d = fmaf(z[k], __ldg(&cr[k]), d);
    return d - 0.5f * __ldg(&g_csq[idx]);
}
static __device__ __forceinline__ bool better(float sa, int ia, float sb, int ib) {
    return sa > sb || (sa == sb && ia < ib);
}

// ================= Kernel 1: z = x @ U (FFMA2, swizzled transpose) =================
__global__ void __launch_bounds__(NTHR, 4)
phaseA_kernel(const float* __restrict__ x,
              const float* __restrict__ U,
              float* __restrict__ out,
              int B)
{
    __shared__ float xs_t[KT * XS_STRIDE];   // 16896 B
    __shared__ float us[KT * 64];            // 8192 B

    const int tid = threadIdx.x;
    const int R0  = blockIdx.x * ROWS;
    const int ty  = tid >> 3;
    const int tx  = tid & 7;
    const size_t Z_OFF = (size_t)B * DDIM;

    u64 acc2[8][4];
    #pragma unroll
    for (int i = 0; i < 8; i++)
        #pragma unroll
        for (int p = 0; p < 4; p++) acc2[i][p] = 0ull;

    const float4* x4 = (const float4*)x;
    const float4* U4 = (const float4*)U;

    for (int kk = 0; kk < DDIM; kk += KT) {
        // x tile transposed with 4-row-chunk XOR swizzle (conflict-free stores)
        #pragma unroll
        for (int j = 0; j < 8; j++) {
            int l4  = j * NTHR + tid;
            int row = l4 >> 3;               // 0..127
            int k4  = l4 & 7;                // 0..7
            float4 v = x4[(size_t)(R0 + row) * (DDIM / 4) + (kk >> 2) + k4];
            int sw = ((row >> 2) ^ k4) * 4 + (row & 3);   // swizzled position
            xs_t[(4 * k4 + 0) * XS_STRIDE + sw] = v.x;
            xs_t[(4 * k4 + 1) * XS_STRIDE + sw] = v.y;
            xs_t[(4 * k4 + 2) * XS_STRIDE + sw] = v.z;
            xs_t[(4 * k4 + 3) * XS_STRIDE + sw] = v.w;
        }
        #pragma unroll
        for (int j = 0; j < 4; j++) {
            int l4 = j * NTHR + tid;
            int kr = l4 >> 4;
            int c4 = l4 & 15;
            ((float4*)us)[kr * 16 + c4] = U4[(kk + kr) * 16 + c4];
        }
        __syncthreads();
        #pragma unroll 2
        for (int k2 = 0; k2 < 8; k2++) {     // groups of 4 k with fixed swizzle const
            const int c0 = ((2 * ty) ^ k2) * 4;
            const int c1 = ((2 * ty + 1) ^ k2) * 4;
            #pragma unroll
            for (int kc = 0; kc < 4; kc++) {
                int k = k2 * 4 + kc;
                float4 a0 = *(const float4*)&xs_t[k * XS_STRIDE + c0];
                float4 a1 = *(const float4*)&xs_t[k * XS_STRIDE + c1];
                ulonglong2 b01 = *(const ulonglong2*)&us[k * 64 + tx * 8];
                ulonglong2 b23 = *(const ulonglong2*)&us[k * 64 + tx * 8 + 4];
                u64 bp[4] = {b01.x, b01.y, b23.x, b23.y};
                float a[8] = {a0.x, a0.y, a0.z, a0.w, a1.x, a1.y, a1.z, a1.w};
                #pragma unroll
                for (int i = 0; i < 8; i++) {
                    u64 ad = pk2(a[i], a[i]);
                    #pragma unroll
                    for (int p = 0; p < 4; p++) ffma2(acc2[i][p], ad, bp[p]);
                }
            }
        }
        __syncthreads();
    }

    // z -> gmem (coalesced float4 pairs)
    float4* oz = (float4*)(out + Z_OFF);
    #pragma unroll
    for (int i = 0; i < 8; i++) {
        int row = ty * 8 + i;
        float2 v0 = upk2(acc2[i][0]), v1 = upk2(acc2[i][1]);
        float2 v2 = upk2(acc2[i][2]), v3 = upk2(acc2[i][3]);
        oz[(size_t)(R0 + row) * 16 + tx * 2]     = make_float4(v0.x, v0.y, v1.x, v1.y);
        oz[(size_t)(R0 + row) * 16 + tx * 2 + 1] = make_float4(v2.x, v2.y, v3.x, v3.y);
    }
}

// ================= Kernel 2: HMMA scores + argmin + outputs =================
__global__ void __launch_bounds__(NTHR, 4)
phaseBC_kernel(const float* __restrict__ cb,
               float* __restrict__ out,
               int B)
{
    extern __shared__ char smc[];
    uint32_t* AH    = (uint32_t*)(smc + SM_AH);
    uint32_t* AL    = (uint32_t*)(smc + SM_AL);
    uint32_t* BH    = (uint32_t*)(smc + SM_BH);
    uint32_t* BL    = (uint32_t*)(smc + SM_BL);
    float*    csq2s = (float*)(smc + SM_CSQ);
    int*      sidx  = (int*)(smc + SM_SIDX);

    const int tid = threadIdx.x;
    const int R0  = blockIdx.x * ROWS;
    const uint32_t sbase = smem_u32_of(smc);

    const size_t Z_OFF   = (size_t)B * DDIM;
    const size_t ZQ_OFF  = Z_OFF + (size_t)B * KLAT;
    const size_t IDX_OFF = ZQ_OFF + (size_t)B * KLAT;
    const float* zg = out + Z_OFF;

    // Build A planes from z (coalesced gmem reads, vectorized smem stores)
    {
        const float4* z4 = (const float4*)(zg + (size_t)R0 * KLAT);
        #pragma unroll
        for (int j = 0; j < 16; j++) {
            int idx = j * NTHR + tid;        // 0..2047
            int row = idx >> 4;
            int c4  = idx & 15;              // float4 index within row
            float4 v = z4[idx];
            float h0 = __bfloat162float(__float2bfloat16(v.x));
            float h1 = __bfloat162float(__float2bfloat16(v.y));
            float h2 = __bfloat162float(__float2bfloat16(v.z));
            float h3 = __bfloat162float(__float2bfloat16(v.w));
            uint2 hw = make_uint2(pack_bf16x2(v.x, v.y), pack_bf16x2(v.z, v.w));
            uint2 lw = make_uint2(pack_bf16x2(v.x - h0, v.y - h1),
                                  pack_bf16x2(v.z - h2, v.w - h3));
            *(uint2*)&AH[row * PW + 2 * c4] = hw;
            *(uint2*)&AL[row * PW + 2 * c4] = lw;
        }
    }
    __syncthreads();

    const int lane = tid & 31;
    const int w    = tid >> 5;
    const int g    = lane >> 2;
    const int t    = lane & 3;

    const uint32_t rowA_off = (uint32_t)((w * 32 + ((lane >> 3) & 1) * 8 + (lane & 7)) * 144
                                         + ((lane >> 4) & 1) * 16);
    const uint32_t rowB_off = (uint32_t)((((lane >> 4) & 1) * 8 + (lane & 7)) * 144
                                         + ((lane >> 3) & 1) * 16);
    const uint32_t AHs = sbase + SM_AH, ALs = sbase + SM_AL;
    const uint32_t BHs = sbase + SM_BH, BLs = sbase + SM_BL;

    u64 key1[4], key2[4];
    #pragma unroll
    for (int s = 0; s < 4; s++) { key1[s] = 0ull; key2[s] = 0ull; }

    for (int ct = 0; ct < NCODE; ct += 64) {
        // load 64-code tile (hi+lo planes): 1024 uint4 total, coalesced-ish
        {
            #pragma unroll
            for (int j = 0; j < 8; j++) {
                int idx = j * NTHR + tid;    // 0..1023
                int pl  = idx >> 9;          // 0: hi, 1: lo
                int r   = (idx & 511) >> 3;  // 0..63
                int c   = idx & 7;
                const uint4* src = pl ? (const uint4*)(g_cbl + (size_t)(ct + r) * KLAT)
                                      : (const uint4*)(g_cbh + (size_t)(ct + r) * KLAT);
                uint32_t* dst = pl ? BL : BH;
                *(uint4*)&dst[r * PW + c * 4] = src[c];
            }
            if (tid < 64) csq2s[tid] = 0.5f * g_csq[ct + tid];
        }
        __syncthreads();

        #pragma unroll 1
        for (int pass = 0; pass < 2; pass++) {
            float D[2][4][4];
            #pragma unroll
            for (int m = 0; m < 2; m++)
                #pragma unroll
                for (int n8 = 0; n8 < 4; n8++)
                    #pragma unroll
                    for (int q = 0; q < 4; q++) D[m][n8][q] = 0.f;

            #pragma unroll
            for (int k = 0; k < 4; k++) {
                uint32_t ah[2][4], al[2][4];
                #pragma unroll
                for (int m = 0; m < 2; m++) {
                    ldsm_x4(ah[m], AHs + rowA_off + m * 2304 + k * 32);
                    ldsm_x4(al[m], ALs + rowA_off + m * 2304 + k * 32);
                }
                #pragma unroll
                for (int j = 0; j < 2; j++) {
                    uint32_t bh[4], bl[4];
                    uint32_t bo = (uint32_t)((pass * 32 + j * 16) * 144 + k * 32);
                    ldsm_x4(bh, BHs + rowB_off + bo);
                    ldsm_x4(bl, BLs + rowB_off + bo);
                    #pragma unroll
                    for (int m = 0; m < 2; m++) {
                        MMA_BF16(D[m][2 * j],     ah[m], bh[0], bh[1]);
                        MMA_BF16(D[m][2 * j],     al[m], bh[0], bh[1]);
                        MMA_BF16(D[m][2 * j],     ah[m], bl[0], bl[1]);
                        MMA_BF16(D[m][2 * j + 1], ah[m], bh[2], bh[3]);
                        MMA_BF16(D[m][2 * j + 1], al[m], bh[2], bh[3]);
                        MMA_BF16(D[m][2 * j + 1], ah[m], bl[2], bl[3]);
                    }
                }
            }

            // branchless pair-keyed top-2
            #pragma unroll
            for (int n8 = 0; n8 < 4; n8++) {
                int cl_ = pass * 32 + n8 * 8 + 2 * t;
                float2 cq = *(const float2*)&csq2s[cl_];
                int pid = (ct + cl_) >> 1;
                #pragma unroll
                for (int m = 0; m < 2; m++) {
                    float s0 = fmaxf(D[m][n8][0] - cq.x, D[m][n8][1] - cq.y);
                    upd2(key1[m * 2],     key2[m * 2],     s0, pid);
                    float s1 = fmaxf(D[m][n8][2] - cq.x, D[m][n8][3] - cq.y);
                    upd2(key1[m * 2 + 1], key2[m * 2 + 1], s1, pid);
                }
            }
        }
        __syncthreads();
    }

    // merge top-2 keys across the 4 threads sharing each row
    #pragma unroll
    for (int s = 0; s < 4; s++) {
        #pragma unroll
        for (int off = 2; off > 0; off >>= 1) {
            u64 k1b = __shfl_down_sync(0xffffffffu, key1[s], off, 4);
            u64 k2b = __shfl_down_sync(0xffffffffu, key2[s], off, 4);
            u64 m1 = key1[s] > k1b ? key1[s] : k1b;
            u64 lo = key1[s] > k1b ? k1b : key1[s];
            u64 mm = key2[s] > k2b ? key2[s] : k2b;
            key2[s] = lo > mm ? lo : mm;
            key1[s] = m1;
        }
    }
    if (t == 0) {
        #pragma unroll
        for (int s = 0; s < 4; s++) {
            int row = w * 32 + (s >> 1) * 16 + (s & 1) * 8 + g;
            const float* zr = zg + (size_t)(R0 + row) * KLAT;
            int pid1 = 511 - (int)(uint32_t)key1[s];
            int c1 = pid1 * 2;
            float ea = exact_sc(zr, cb, c1);
            float eb = exact_sc(zr, cb, c1 + 1);
            int   fi = (eb > ea) ? (c1 + 1) : c1;
            float fe = (eb > ea) ? eb : ea;
            float s1f = unkey((uint32_t)(key1[s] >> 32));
            float s2f = unkey((uint32_t)(key2[s] >> 32));
            if (s1f - s2f < 1e-2f) {
                int pid2 = 511 - (int)(uint32_t)key2[s];
                int c2 = pid2 * 2;
                float ec = exact_sc(zr, cb, c2);
                float ed = exact_sc(zr, cb, c2 + 1);
                if (better(ec, c2,     fe, fi)) { fe = ec; fi = c2; }
                if (better(ed, c2 + 1, fe, fi)) { fe = ed; fi = c2 + 1; }
            }
            sidx[row] = fi;
        }
    }
    __syncthreads();

    // Phase C: outputs [x_recon | z_q_ste | indices]
    out[IDX_OFF + R0 + tid] = (float)sidx[tid];

    const int lane2 = tid & 31;
    const float2* cb2  = (const float2*)cb;
    const float4* dec4 = (const float4*)g_dec;
    float2* ozq = (float2*)(out + ZQ_OFF);
    float4* ox  = (float4*)out;
    for (int r = 0; r < 32; r++) {
        int row = w * 32 + r;
        int idx = sidx[row];
        float2 zv = *(const float2*)(zg + (size_t)(R0 + row) * KLAT + 2 * lane2);
        float2 cv = cb2[(size_t)idx * (KLAT / 2) + lane2];
        float2 o;
        o.x = zv.x + (cv.x - zv.x);          // STE numerics
        o.y = zv.y + (cv.y - zv.y);
        ozq[(size_t)(R0 + row) * (KLAT / 2) + lane2] = o;
        #pragma unroll
        for (int j = 0; j < 4; j++)
            ox[(size_t)(R0 + row) * (DDIM / 4) + j * 32 + lane2] =
                dec4[(size_t)idx * (DDIM / 4) + j * 32 + lane2];
    }
}

extern "C" void kernel_launch(void* const* d_in, const int* in_sizes, int n_in,
                              void* d_out, int out_size) {
    const float *x = 0, *U = 0, *cb = 0;
    int xsize = 0;
    for (int i = 0; i < n_in; i++) {
        if (in_sizes[i] == DDIM * KLAT)       U  = (const float*)d_in[i];
        else if (in_sizes[i] == NCODE * KLAT) cb = (const float*)d_in[i];
        else { x = (const float*)d_in[i]; xsize = in_sizes[i]; }
    }
    float* out = (float*)d_out;
    const int B = xsize / DDIM;

    cudaFuncSetAttribute(phaseBC_kernel, cudaFuncAttributeMaxDynamicSharedMemorySize, SM_TOTAL);
    prep_kernel<<<NCODE, 128>>>(U, cb);
    phaseA_kernel<<<B / ROWS, NTHR>>>(x, U, out, B);
    phaseBC_kernel<<<B / ROWS, NTHR, SM_TOTAL>>>(cb, out, B);
}